// round 14
// baseline (speedup 1.0000x reference)
#include <cuda_runtime.h>
#include <cuda_fp16.h>
#include <math.h>
#include <stdint.h>

#define NROWS 262144
#define NTAB  50001
#define NC    256
#define NTHR  512
#define MROWS 64

// SMEM byte offsets
#define OFF_AHI  0            // 64 x 264 fp16 = 33792
#define OFF_WBUF 33792        // 16 warps x 4 bufs x 1024B = 65536 -> 99328
#define OFF_CROW 99328        // 64 x 4 floats -> 100352
#define SM_REQ   100352
#define ASTR 264

__device__ __align__(16) __half g_wT[4][2][65536]; // [vert0,vert1,view0,view1][hi,lo][n*256+k]
__device__ __align__(16) __half g_wP[2][16384];    // proj [hi,lo][n*64+k]
__device__ float g_cWd[1536], g_aWd[256], g_cbd[3], g_abd;
__device__ float g_bias[1280];   // vert_b(512) | b_proj(256) | view_b(512)
__device__ float g_scale[8 * NTAB];  // precomputed max_norm scales

// ---------------- low-level helpers ----------------
__device__ __forceinline__ uint32_t smem_u32(const void* p) {
    uint32_t a;
    asm("{ .reg .u64 t; cvta.to.shared.u64 t, %1; cvt.u32.u64 %0, t; }" : "=r"(a) : "l"(p));
    return a;
}
__device__ __forceinline__ void ldsm4(uint32_t r[4], uint32_t a) {
    asm volatile("ldmatrix.sync.aligned.m8n8.x4.shared.b16 {%0,%1,%2,%3}, [%4];"
        : "=r"(r[0]), "=r"(r[1]), "=r"(r[2]), "=r"(r[3]) : "r"(a));
}
__device__ __forceinline__ void mma16816(float c[4], const uint32_t a[4], uint32_t b0, uint32_t b1) {
    asm volatile("mma.sync.aligned.m16n8k16.row.col.f32.f16.f16.f32 "
        "{%0,%1,%2,%3},{%4,%5,%6,%7},{%8,%9},{%0,%1,%2,%3};"
        : "+f"(c[0]), "+f"(c[1]), "+f"(c[2]), "+f"(c[3])
        : "r"(a[0]), "r"(a[1]), "r"(a[2]), "r"(a[3]), "r"(b0), "r"(b1));
}
__device__ __forceinline__ void cp16(uint32_t d, const void* s) {
    asm volatile("cp.async.cg.shared.global [%0], [%1], 16;" :: "r"(d), "l"(s));
}
__device__ __forceinline__ uint32_t pack_h2(float f0, float f1) {
    __half2 h = __floats2half2_rn(f0, f1);
    return *(uint32_t*)&h;
}

// Warp-private copy: this warp's 16 N-rows x 16 K (hi+lo) -> given ring buffer.
__device__ __forceinline__ void copy_w(uint32_t dst, const __half* srcHi,
        const __half* srcLo, int kfull, int c, int lane, int nb0)
{
#pragma unroll
    for (int q = 0; q < 2; ++q) {
        int idx = q * 32 + lane;
        int mat = idx >> 5, rem = idx & 31, r = rem >> 1, s = rem & 1;
        const __half* src = (mat ? srcLo : srcHi) + (size_t)(nb0 + r) * kfull + c * 16 + s * 8;
        uint32_t off = (uint32_t)(mat * 512 + r * 32 + ((s ^ ((r >> 2) & 1)) << 4));
        cp16(dst + off, src);
    }
    asm volatile("cp.async.commit_group;");
}

// ---------------- prep kernels ----------------
__global__ void prep_norm(const float* __restrict__ emb) {
    int gid = blockIdx.x * 8 + (threadIdx.x >> 5);
    int lane = threadIdx.x & 31;
    if (gid >= 8 * NTAB) return;
    const float* ep = emb + (size_t)gid * NC + lane * 8;
    float4 e0 = *(const float4*)ep, e1 = *(const float4*)(ep + 4);
    float ss = e0.x*e0.x + e0.y*e0.y + e0.z*e0.z + e0.w*e0.w
             + e1.x*e1.x + e1.y*e1.y + e1.z*e1.z + e1.w*e1.w;
#pragma unroll
    for (int o = 16; o > 0; o >>= 1) ss += __shfl_xor_sync(~0u, ss, o);
    if (lane == 0) {
        float nrm = sqrtf(ss);
        g_scale[gid] = (nrm > 1.f) ? 1.f / fmaxf(nrm, 1e-7f) : 1.f;
    }
}

__global__ void prep_kernel(const float* __restrict__ w_proj, const float* __restrict__ view_W,
                            const float* __restrict__ vert_W,
                            const float* __restrict__ aW1, const float* __restrict__ ab1,
                            const float* __restrict__ aW2, const float* __restrict__ ab2,
                            const float* __restrict__ cW1, const float* __restrict__ cb1,
                            const float* __restrict__ cW2, const float* __restrict__ cb2,
                            const float* __restrict__ b_proj, const float* __restrict__ view_b,
                            const float* __restrict__ vert_b)
{
    int t = blockIdx.x * blockDim.x + threadIdx.x;
    if (t < 262144) {
        int layer = t >> 16, e = t & 65535, n = e >> 8, k = e & 255;
        const float* W = (layer < 2) ? (vert_W + layer * 65536) : (view_W + (layer - 2) * 65536);
        float w = W[k * 256 + n];
        __half hb = __float2half_rn(w);
        g_wT[layer][0][n * 256 + k] = hb;
        g_wT[layer][1][n * 256 + k] = __float2half_rn(w - __half2float(hb));
    } else if (t < 262144 + 16384) {
        int e = t - 262144, n = e >> 6, k = e & 63;
        float w = (k < 36) ? w_proj[k * 256 + n] : 0.f;
        __half hb = __float2half_rn(w);
        g_wP[0][n * 64 + k] = hb;
        g_wP[1][n * 64 + k] = __float2half_rn(w - __half2float(hb));
    } else if (t < 262144 + 16384 + 1536) {
        int e = t - 262144 - 16384, kk = e / 3, j = e - kk * 3;
        float s = 0.f;
        for (int m = 0; m < 512; ++m) s += cW1[kk * 512 + m] * cW2[m * 3 + j];
        g_cWd[e] = s;
    } else if (t < 262144 + 16384 + 1536 + 3) {
        int j = t - 262144 - 16384 - 1536;
        float s = cb2[j];
        for (int m = 0; m < 512; ++m) s += cb1[m] * cW2[m * 3 + j];
        g_cbd[j] = s;
    } else if (t < 262144 + 16384 + 1536 + 3 + 256) {
        int kk = t - 262144 - 16384 - 1536 - 3;
        float s = 0.f;
        for (int m = 0; m < 256; ++m) s += aW1[kk * 256 + m] * aW2[m];
        g_aWd[kk] = s;
    } else if (t == 262144 + 16384 + 1536 + 3 + 256) {
        float s = ab2[0];
        for (int m = 0; m < 256; ++m) s += ab1[m] * aW2[m];
        g_abd = s;
    } else if (t >= 280064 && t < 280064 + 1280) {
        int i = t - 280064;
        float v;
        if (i < 512) v = vert_b[i];
        else if (i < 768) v = b_proj[i - 512];
        else v = view_b[i - 768];
        g_bias[i] = v;
    }
}

// ---------------- warp-autonomous fused layer (4-deep ring pipeline) ----------------
// fp16 2-pass: acc += Ah*Wh + Ah*Wl
// Precondition: chunks 0..2 of THIS layer already committed into ring bufs 0..2.
// Postcondition (if nxHi): chunks 0..2 of next layer committed into bufs 0..2.
// MODE 0: store relu; 1: store no-relu; 2: alpha head (relu); 3: color head (relu)
template<int KFULL, int MODE>
__device__ void do_layer(char* sm, uint32_t smb,
    const __half* __restrict__ WgHi, const __half* __restrict__ WgLo,
    const float* __restrict__ bias,
    const __half* nxHi, const __half* nxLo, int nxK)
{
    const int tid = threadIdx.x, lane = tid & 31, w = tid >> 5;
    const int nb0 = w * 16;
    const int rowin = lane & 7, tsel = lane >> 3;

    float acc[4][2][4];
#pragma unroll
    for (int mt = 0; mt < 4; ++mt)
#pragma unroll
        for (int h = 0; h < 2; ++h)
#pragma unroll
            for (int j = 0; j < 4; ++j) acc[mt][h][j] = 0.f;

    const uint32_t aoffH = smb + OFF_AHI +
        (uint32_t)((rowin + (tsel & 1) * 8) * ASTR + (tsel >> 1) * 8) * 2;
    const int rowB = rowin + (tsel >> 1) * 8;
    const uint32_t woffs = (uint32_t)(rowB * 32 + (((tsel & 1) ^ ((rowB >> 2) & 1)) << 4));
    const uint32_t wreg = smb + OFF_WBUF + (uint32_t)w * 4096;

    const int nch = KFULL / 16;   // always a multiple of 4
    for (int c = 0; c < nch; ++c) {
        // A-fragments first: independent of the W ring, overlaps the wait
        uint32_t ah[4][4];
        const uint32_t kg2 = (uint32_t)c * 32;
#pragma unroll
        for (int mt = 0; mt < 4; ++mt)
            ldsm4(ah[mt], aoffH + kg2 + (uint32_t)mt * (16 * ASTR * 2));

        // issue chunk c+3 (this layer, next layer, or empty to keep count)
        int f = c + 3;
        uint32_t nbuf = wreg + (uint32_t)(f & 3) * 1024;
        if (f < nch)                      copy_w(nbuf, WgHi, WgLo, KFULL, f, lane, nb0);
        else if (nxHi && f - nch < 3)     copy_w(nbuf, nxHi, nxLo, nxK, f - nch, lane, nb0);
        else                              asm volatile("cp.async.commit_group;");

        asm volatile("cp.async.wait_group 3;" ::: "memory");
        __syncwarp();

        const uint32_t wb = wreg + (uint32_t)(c & 3) * 1024;
        uint32_t wh[4], wl[4];
        ldsm4(wh, wb + woffs);
        ldsm4(wl, wb + 512 + woffs);
#pragma unroll
        for (int mt = 0; mt < 4; ++mt) {
            mma16816(acc[mt][0], ah[mt], wh[0], wh[1]);
            mma16816(acc[mt][0], ah[mt], wl[0], wl[1]);
            mma16816(acc[mt][1], ah[mt], wh[2], wh[3]);
            mma16816(acc[mt][1], ah[mt], wl[2], wl[3]);
        }
    }

    // ---- epilogue (2 CTA barriers per layer) ----
    __syncthreads();   // all warps done reading A
    __half* AHI = (__half*)(sm + OFF_AHI);
    float* crow = (float*)(sm + OFF_CROW);

#pragma unroll
    for (int mt = 0; mt < 4; ++mt) {
        int r0 = mt * 16 + (lane >> 2), r1 = r0 + 8;
        float pa0 = 0.f, pa1 = 0.f;
        float pc0[3] = {0.f, 0.f, 0.f}, pc1[3] = {0.f, 0.f, 0.f};
#pragma unroll
        for (int h = 0; h < 2; ++h) {
            int col = nb0 + h * 8 + (lane & 3) * 2;
            float* d = acc[mt][h];
            float b0 = __ldg(bias + col), b1 = __ldg(bias + col + 1);
            float f0 = d[0] + b0, f1 = d[1] + b1;
            float f2 = d[2] + b0, f3 = d[3] + b1;
            if (MODE != 1) {
                f0 = fmaxf(f0, 0.f); f1 = fmaxf(f1, 0.f);
                f2 = fmaxf(f2, 0.f); f3 = fmaxf(f3, 0.f);
            }
            if (MODE <= 1) {
                *(uint32_t*)(AHI + r0 * ASTR + col) = pack_h2(f0, f1);
                *(uint32_t*)(AHI + r1 * ASTR + col) = pack_h2(f2, f3);
            } else if (MODE == 2) {
                float w0 = __ldg(g_aWd + col), w1 = __ldg(g_aWd + col + 1);
                pa0 += f0 * w0 + f1 * w1;
                pa1 += f2 * w0 + f3 * w1;
            } else {
#pragma unroll
                for (int j = 0; j < 3; ++j) {
                    float w0 = __ldg(g_cWd + col * 3 + j), w1 = __ldg(g_cWd + (col + 1) * 3 + j);
                    pc0[j] += f0 * w0 + f1 * w1;
                    pc1[j] += f2 * w0 + f3 * w1;
                }
            }
        }
        if (MODE == 2) {
            pa0 += __shfl_xor_sync(~0u, pa0, 1); pa0 += __shfl_xor_sync(~0u, pa0, 2);
            pa1 += __shfl_xor_sync(~0u, pa1, 1); pa1 += __shfl_xor_sync(~0u, pa1, 2);
            if ((lane & 3) == 0) {
                atomicAdd(crow + r0 * 4 + 3, pa0);
                atomicAdd(crow + r1 * 4 + 3, pa1);
            }
        } else if (MODE == 3) {
#pragma unroll
            for (int j = 0; j < 3; ++j) {
                pc0[j] += __shfl_xor_sync(~0u, pc0[j], 1); pc0[j] += __shfl_xor_sync(~0u, pc0[j], 2);
                pc1[j] += __shfl_xor_sync(~0u, pc1[j], 1); pc1[j] += __shfl_xor_sync(~0u, pc1[j], 2);
            }
            if ((lane & 3) == 0) {
#pragma unroll
                for (int j = 0; j < 3; ++j) {
                    atomicAdd(crow + r0 * 4 + j, pc0[j]);
                    atomicAdd(crow + r1 * 4 + j, pc1[j]);
                }
            }
        }
    }
    __syncthreads();   // A writes visible to all warps
}

// ---------------- main kernel ----------------
__global__ void __launch_bounds__(NTHR, 2)
mesh_main(const int* __restrict__ verts, const float* __restrict__ barys,
          const float* __restrict__ views, const float* __restrict__ emb,
          float* __restrict__ out)
{
    extern __shared__ char sm[];
    uint32_t smb = smem_u32(sm);
    const int tid = threadIdx.x, lane = tid & 31, w = tid >> 5;
    const int base = blockIdx.x * MROWS;

    __half* AHI = (__half*)(sm + OFF_AHI);
    float* crow = (float*)(sm + OFF_CROW);

    // warp-private prefetch of layer-0 chunks 0..2 (overlaps gather)
    {
        uint32_t wreg = smb + OFF_WBUF + (uint32_t)w * 4096;
        copy_w(wreg,        g_wT[0][0], g_wT[0][1], 256, 0, lane, w * 16);
        copy_w(wreg + 1024, g_wT[0][0], g_wT[0][1], 256, 1, lane, w * 16);
        copy_w(wreg + 2048, g_wT[0][0], g_wT[0][1], 256, 2, lane, w * 16);
    }

    if (tid < MROWS) {
        crow[tid * 4 + 0] = g_cbd[0]; crow[tid * 4 + 1] = g_cbd[1];
        crow[tid * 4 + 2] = g_cbd[2]; crow[tid * 4 + 3] = g_abd;
    }

    // ---- single-pass gather: blend (precomputed scales) -> fp16, color partials ----
    for (int r = w; r < MROWS; r += 16) {
        int grow = base + r;
        float v[8];
#pragma unroll
        for (int j = 0; j < 8; ++j) v[j] = 0.f;
#pragma unroll
        for (int vt = 0; vt < 3; ++vt) {
            int idx = verts[grow * 3 + vt] + 1;
            float s = barys[grow * 3 + vt] * __ldg(g_scale + (grow & 7) * NTAB + idx);
            const float* ep = emb + ((size_t)(grow & 7) * NTAB + (size_t)idx) * NC + lane * 8;
            float4 e0 = *(const float4*)ep, e1 = *(const float4*)(ep + 4);
            v[0] += s*e0.x; v[1] += s*e0.y; v[2] += s*e0.z; v[3] += s*e0.w;
            v[4] += s*e1.x; v[5] += s*e1.y; v[6] += s*e1.z; v[7] += s*e1.w;
        }
        int cbase = lane * 8;
#pragma unroll
        for (int p = 0; p < 4; ++p)
            *(uint32_t*)(AHI + r * ASTR + cbase + 2 * p) = pack_h2(v[2 * p], v[2 * p + 1]);
        float p0 = 0.f, p1 = 0.f, p2 = 0.f;
#pragma unroll
        for (int j = 0; j < 8; ++j) {
            const float* w3 = g_cWd + (size_t)(256 + cbase + j) * 3;
            p0 += v[j] * __ldg(w3); p1 += v[j] * __ldg(w3 + 1); p2 += v[j] * __ldg(w3 + 2);
        }
#pragma unroll
        for (int o = 16; o > 0; o >>= 1) {
            p0 += __shfl_xor_sync(~0u, p0, o);
            p1 += __shfl_xor_sync(~0u, p1, o);
            p2 += __shfl_xor_sync(~0u, p2, o);
        }
        if (lane == 0) {
            crow[r * 4 + 0] += p0; crow[r * 4 + 1] += p1; crow[r * 4 + 2] += p2;
        }
    }
    __syncthreads();

    // ---- vert branch ----
    do_layer<256, 0>(sm, smb, g_wT[0][0], g_wT[0][1], g_bias,       g_wT[1][0], g_wT[1][1], 256);
    do_layer<256, 2>(sm, smb, g_wT[1][0], g_wT[1][1], g_bias + 256, g_wP[0],    g_wP[1],    64);

    // ---- sincos -> A buf (K padded to 64) ----
    if (tid < MROWS) {
        int row = base + tid;
        float x0 = views[row * 3], x1 = views[row * 3 + 1], x2 = views[row * 3 + 2];
        float em[36];
#pragma unroll
        for (int l = 0; l < 6; ++l) {
            float f = (float)(1 << l);
            em[l * 6 + 0] = sinf(f * x0); em[l * 6 + 1] = sinf(f * x1); em[l * 6 + 2] = sinf(f * x2);
            em[l * 6 + 3] = cosf(f * x0); em[l * 6 + 4] = cosf(f * x1); em[l * 6 + 5] = cosf(f * x2);
        }
#pragma unroll
        for (int p = 0; p < 18; ++p)
            *(uint32_t*)(AHI + tid * ASTR + 2 * p) = pack_h2(em[2 * p], em[2 * p + 1]);
#pragma unroll
        for (int p = 18; p < 32; ++p)
            *(uint32_t*)(AHI + tid * ASTR + 2 * p) = 0u;
    }
    __syncthreads();

    // ---- view branch ----
    do_layer<64, 1>(sm, smb, g_wP[0], g_wP[1], g_bias + 512,          g_wT[2][0], g_wT[2][1], 256);
    do_layer<256, 0>(sm, smb, g_wT[2][0], g_wT[2][1], g_bias + 768,   g_wT[3][0], g_wT[3][1], 256);
    do_layer<256, 3>(sm, smb, g_wT[3][0], g_wT[3][1], g_bias + 1024,  (const __half*)0, (const __half*)0, 0);

    if (tid < MROWS) {
        float4 ov = make_float4(crow[tid * 4 + 0], crow[tid * 4 + 1],
                                crow[tid * 4 + 2], crow[tid * 4 + 3]);
        *(float4*)(out + (size_t)(base + tid) * 4) = ov;
    }
}

extern "C" void kernel_launch(void* const* d_in, const int* in_sizes, int n_in,
                              void* d_out, int out_size)
{
    const int*   verts  = (const int*)  d_in[0];
    const float* barys  = (const float*)d_in[1];
    const float* views  = (const float*)d_in[2];
    const float* emb    = (const float*)d_in[3];
    const float* w_proj = (const float*)d_in[4];
    const float* b_proj = (const float*)d_in[5];
    const float* view_W = (const float*)d_in[6];
    const float* view_b = (const float*)d_in[7];
    const float* vert_W = (const float*)d_in[8];
    const float* vert_b = (const float*)d_in[9];
    const float* aW1    = (const float*)d_in[10];
    const float* ab1    = (const float*)d_in[11];
    const float* aW2    = (const float*)d_in[12];
    const float* ab2    = (const float*)d_in[13];
    const float* cW1    = (const float*)d_in[14];
    const float* cb1    = (const float*)d_in[15];
    const float* cW2    = (const float*)d_in[16];
    const float* cb2    = (const float*)d_in[17];
    float* out = (float*)d_out;

    prep_norm<<<(8 * NTAB + 7) / 8, 256>>>(emb);
    prep_kernel<<<1100, 256>>>(w_proj, view_W, vert_W, aW1, ab1, aW2, ab2,
                               cW1, cb1, cW2, cb2, b_proj, view_b, vert_b);

    cudaFuncSetAttribute(mesh_main, cudaFuncAttributeMaxDynamicSharedMemorySize, SM_REQ);
    mesh_main<<<NROWS / MROWS, NTHR, SM_REQ>>>(verts, barys, views, emb, out);
}

// round 15
// speedup vs baseline: 1.2118x; 1.2118x over previous
#include <cuda_runtime.h>
#include <cuda_fp16.h>
#include <math.h>
#include <stdint.h>

#define NROWS 262144
#define NTAB  50001
#define NC    256
#define NTHR  512
#define MROWS 64

// SMEM byte offsets
#define OFF_AHI  0            // 64 x 264 fp16 = 33792
#define OFF_WBUF 33792        // 16 warps x 2 bufs x 2048B = 65536 -> 99328
#define OFF_CROW 99328        // 64 x 4 floats -> 100352
#define SM_REQ   100352
#define ASTR 264

__device__ __align__(16) __half g_wT[4][2][65536]; // [vert0,vert1,view0,view1][hi,lo][n*256+k]
__device__ __align__(16) __half g_wP[2][16384];    // proj [hi,lo][n*64+k]
__device__ float g_cWd[1536], g_aWd[256], g_cbd[3], g_abd;
__device__ float g_bias[1280];   // vert_b(512) | b_proj(256) | view_b(512)
__device__ float g_scale[8 * NTAB];  // precomputed max_norm scales

// ---------------- low-level helpers ----------------
__device__ __forceinline__ uint32_t smem_u32(const void* p) {
    uint32_t a;
    asm("{ .reg .u64 t; cvta.to.shared.u64 t, %1; cvt.u32.u64 %0, t; }" : "=r"(a) : "l"(p));
    return a;
}
__device__ __forceinline__ void ldsm4(uint32_t r[4], uint32_t a) {
    asm volatile("ldmatrix.sync.aligned.m8n8.x4.shared.b16 {%0,%1,%2,%3}, [%4];"
        : "=r"(r[0]), "=r"(r[1]), "=r"(r[2]), "=r"(r[3]) : "r"(a));
}
__device__ __forceinline__ void mma16816(float c[4], const uint32_t a[4], uint32_t b0, uint32_t b1) {
    asm volatile("mma.sync.aligned.m16n8k16.row.col.f32.f16.f16.f32 "
        "{%0,%1,%2,%3},{%4,%5,%6,%7},{%8,%9},{%0,%1,%2,%3};"
        : "+f"(c[0]), "+f"(c[1]), "+f"(c[2]), "+f"(c[3])
        : "r"(a[0]), "r"(a[1]), "r"(a[2]), "r"(a[3]), "r"(b0), "r"(b1));
}
__device__ __forceinline__ void cp16(uint32_t d, const void* s) {
    asm volatile("cp.async.cg.shared.global [%0], [%1], 16;" :: "r"(d), "l"(s));
}
__device__ __forceinline__ uint32_t pack_h2(float f0, float f1) {
    __half2 h = __floats2half2_rn(f0, f1);
    return *(uint32_t*)&h;
}

// Warp-private copy: this warp's 16 N-rows x 32 K (hi+lo) -> given 2KB ring buffer.
// Row pitch 64B; 16B unit s of row r swizzled to ((s ^ ((r>>1)&3))<<4).
__device__ __forceinline__ void copy_w32(uint32_t dst, const __half* srcHi,
        const __half* srcLo, int kfull, int c, int lane, int nb0)
{
#pragma unroll
    for (int q = 0; q < 4; ++q) {
        int idx = q * 32 + lane;
        int mat = idx >> 6, rem = idx & 63, r = rem >> 2, s = rem & 3;
        const __half* src = (mat ? srcLo : srcHi) + (size_t)(nb0 + r) * kfull + c * 32 + s * 8;
        uint32_t off = (uint32_t)(mat * 1024 + r * 64 + ((s ^ ((r >> 1) & 3)) << 4));
        cp16(dst + off, src);
    }
    asm volatile("cp.async.commit_group;");
}

// ---------------- prep kernels ----------------
__global__ void prep_norm(const float* __restrict__ emb) {
    int gid = blockIdx.x * 8 + (threadIdx.x >> 5);
    int lane = threadIdx.x & 31;
    if (gid >= 8 * NTAB) return;
    const float* ep = emb + (size_t)gid * NC + lane * 8;
    float4 e0 = *(const float4*)ep, e1 = *(const float4*)(ep + 4);
    float ss = e0.x*e0.x + e0.y*e0.y + e0.z*e0.z + e0.w*e0.w
             + e1.x*e1.x + e1.y*e1.y + e1.z*e1.z + e1.w*e1.w;
#pragma unroll
    for (int o = 16; o > 0; o >>= 1) ss += __shfl_xor_sync(~0u, ss, o);
    if (lane == 0) {
        float nrm = sqrtf(ss);
        g_scale[gid] = (nrm > 1.f) ? 1.f / fmaxf(nrm, 1e-7f) : 1.f;
    }
}

__global__ void prep_kernel(const float* __restrict__ w_proj, const float* __restrict__ view_W,
                            const float* __restrict__ vert_W,
                            const float* __restrict__ aW1, const float* __restrict__ ab1,
                            const float* __restrict__ aW2, const float* __restrict__ ab2,
                            const float* __restrict__ cW1, const float* __restrict__ cb1,
                            const float* __restrict__ cW2, const float* __restrict__ cb2,
                            const float* __restrict__ b_proj, const float* __restrict__ view_b,
                            const float* __restrict__ vert_b)
{
    int t = blockIdx.x * blockDim.x + threadIdx.x;
    if (t < 262144) {
        int layer = t >> 16, e = t & 65535, n = e >> 8, k = e & 255;
        const float* W = (layer < 2) ? (vert_W + layer * 65536) : (view_W + (layer - 2) * 65536);
        float w = W[k * 256 + n];
        __half hb = __float2half_rn(w);
        g_wT[layer][0][n * 256 + k] = hb;
        g_wT[layer][1][n * 256 + k] = __float2half_rn(w - __half2float(hb));
    } else if (t < 262144 + 16384) {
        int e = t - 262144, n = e >> 6, k = e & 63;
        float w = (k < 36) ? w_proj[k * 256 + n] : 0.f;
        __half hb = __float2half_rn(w);
        g_wP[0][n * 64 + k] = hb;
        g_wP[1][n * 64 + k] = __float2half_rn(w - __half2float(hb));
    } else if (t < 262144 + 16384 + 1536) {
        int e = t - 262144 - 16384, kk = e / 3, j = e - kk * 3;
        float s = 0.f;
        for (int m = 0; m < 512; ++m) s += cW1[kk * 512 + m] * cW2[m * 3 + j];
        g_cWd[e] = s;
    } else if (t < 262144 + 16384 + 1536 + 3) {
        int j = t - 262144 - 16384 - 1536;
        float s = cb2[j];
        for (int m = 0; m < 512; ++m) s += cb1[m] * cW2[m * 3 + j];
        g_cbd[j] = s;
    } else if (t < 262144 + 16384 + 1536 + 3 + 256) {
        int kk = t - 262144 - 16384 - 1536 - 3;
        float s = 0.f;
        for (int m = 0; m < 256; ++m) s += aW1[kk * 256 + m] * aW2[m];
        g_aWd[kk] = s;
    } else if (t == 262144 + 16384 + 1536 + 3 + 256) {
        float s = ab2[0];
        for (int m = 0; m < 256; ++m) s += ab1[m] * aW2[m];
        g_abd = s;
    } else if (t >= 280064 && t < 280064 + 1280) {
        int i = t - 280064;
        float v;
        if (i < 512) v = vert_b[i];
        else if (i < 768) v = b_proj[i - 512];
        else v = view_b[i - 768];
        g_bias[i] = v;
    }
}

// ---------------- warp-autonomous fused layer (16 warps: each M64 x private N16) ----------------
// fp16 2-pass, 32-K chunks, 2-deep ring: acc += Ah*Wh + Ah*Wl
// Precondition: this warp's chunk0 copy already committed (1 group pending).
// Postcondition (if nxHi): next layer's chunk0 committed (1 group pending).
// MODE 0: store relu; 1: store no-relu; 2: alpha head (relu); 3: color head (relu)
template<int KFULL, int MODE>
__device__ void do_layer(char* sm, uint32_t smb,
    const __half* __restrict__ WgHi, const __half* __restrict__ WgLo,
    const float* __restrict__ bias,
    const __half* nxHi, const __half* nxLo, int nxK)
{
    const int tid = threadIdx.x, lane = tid & 31, w = tid >> 5;
    const int nb0 = w * 16;
    const int rowin = lane & 7, tsel = lane >> 3;

    float acc[4][2][4];
#pragma unroll
    for (int mt = 0; mt < 4; ++mt)
#pragma unroll
        for (int h = 0; h < 2; ++h)
#pragma unroll
            for (int j = 0; j < 4; ++j) acc[mt][h][j] = 0.f;

    const uint32_t aoffH = smb + OFF_AHI +
        (uint32_t)((rowin + (tsel & 1) * 8) * ASTR + (tsel >> 1) * 8) * 2;
    const int rowB = rowin + (tsel >> 1) * 8;
    const int sB   = tsel & 1;
    const uint32_t wsw = (uint32_t)((rowB >> 1) & 3);
    const uint32_t woff0 = (uint32_t)(rowB * 64) + (((uint32_t)sB ^ wsw) << 4);
    const uint32_t woff1 = (uint32_t)(rowB * 64) + (((uint32_t)(2 + sB) ^ wsw) << 4);
    const uint32_t wreg = smb + OFF_WBUF + (uint32_t)w * 4096;

    const int nch = KFULL / 32;
    for (int c = 0; c < nch; ++c) {
        int f = c + 1;
        uint32_t nbuf = wreg + (uint32_t)(f & 1) * 2048;
        if (f < nch)      copy_w32(nbuf, WgHi, WgLo, KFULL, f, lane, nb0);
        else if (nxHi)    copy_w32(nbuf, nxHi, nxLo, nxK, 0, lane, nb0);
        else              asm volatile("cp.async.commit_group;");
        asm volatile("cp.async.wait_group 1;" ::: "memory");
        __syncwarp();
        const uint32_t wb = wreg + (uint32_t)(c & 1) * 2048;
#pragma unroll
        for (int kk = 0; kk < 2; ++kk) {
            uint32_t wo = kk ? woff1 : woff0;
            uint32_t wh[4], wl[4];
            ldsm4(wh, wb + wo);
            ldsm4(wl, wb + 1024 + wo);
            const uint32_t kg2 = (uint32_t)(c * 64 + kk * 32);
#pragma unroll
            for (int mt = 0; mt < 4; ++mt) {
                uint32_t ah[4];
                ldsm4(ah, aoffH + kg2 + (uint32_t)mt * (16 * ASTR * 2));
                mma16816(acc[mt][0], ah, wh[0], wh[1]);
                mma16816(acc[mt][0], ah, wl[0], wl[1]);
                mma16816(acc[mt][1], ah, wh[2], wh[3]);
                mma16816(acc[mt][1], ah, wl[2], wl[3]);
            }
        }
    }

    // ---- epilogue (2 CTA barriers per layer) ----
    __syncthreads();   // all warps done reading A
    __half* AHI = (__half*)(sm + OFF_AHI);
    float* crow = (float*)(sm + OFF_CROW);

    // bias values are mt-invariant: hoist
    float bb[2][2];
#pragma unroll
    for (int h = 0; h < 2; ++h) {
        int col = nb0 + h * 8 + (lane & 3) * 2;
        bb[h][0] = __ldg(bias + col);
        bb[h][1] = __ldg(bias + col + 1);
    }

#pragma unroll
    for (int mt = 0; mt < 4; ++mt) {
        int r0 = mt * 16 + (lane >> 2), r1 = r0 + 8;
        float pa0 = 0.f, pa1 = 0.f;
        float pc0[3] = {0.f, 0.f, 0.f}, pc1[3] = {0.f, 0.f, 0.f};
#pragma unroll
        for (int h = 0; h < 2; ++h) {
            int col = nb0 + h * 8 + (lane & 3) * 2;
            float* d = acc[mt][h];
            float f0 = d[0] + bb[h][0], f1 = d[1] + bb[h][1];
            float f2 = d[2] + bb[h][0], f3 = d[3] + bb[h][1];
            if (MODE != 1) {
                f0 = fmaxf(f0, 0.f); f1 = fmaxf(f1, 0.f);
                f2 = fmaxf(f2, 0.f); f3 = fmaxf(f3, 0.f);
            }
            if (MODE <= 1) {
                *(uint32_t*)(AHI + r0 * ASTR + col) = pack_h2(f0, f1);
                *(uint32_t*)(AHI + r1 * ASTR + col) = pack_h2(f2, f3);
            } else if (MODE == 2) {
                float w0 = __ldg(g_aWd + col), w1 = __ldg(g_aWd + col + 1);
                pa0 += f0 * w0 + f1 * w1;
                pa1 += f2 * w0 + f3 * w1;
            } else {
#pragma unroll
                for (int j = 0; j < 3; ++j) {
                    float w0 = __ldg(g_cWd + col * 3 + j), w1 = __ldg(g_cWd + (col + 1) * 3 + j);
                    pc0[j] += f0 * w0 + f1 * w1;
                    pc1[j] += f2 * w0 + f3 * w1;
                }
            }
        }
        if (MODE == 2) {
            pa0 += __shfl_xor_sync(~0u, pa0, 1); pa0 += __shfl_xor_sync(~0u, pa0, 2);
            pa1 += __shfl_xor_sync(~0u, pa1, 1); pa1 += __shfl_xor_sync(~0u, pa1, 2);
            if ((lane & 3) == 0) {
                atomicAdd(crow + r0 * 4 + 3, pa0);
                atomicAdd(crow + r1 * 4 + 3, pa1);
            }
        } else if (MODE == 3) {
#pragma unroll
            for (int j = 0; j < 3; ++j) {
                pc0[j] += __shfl_xor_sync(~0u, pc0[j], 1); pc0[j] += __shfl_xor_sync(~0u, pc0[j], 2);
                pc1[j] += __shfl_xor_sync(~0u, pc1[j], 1); pc1[j] += __shfl_xor_sync(~0u, pc1[j], 2);
            }
            if ((lane & 3) == 0) {
#pragma unroll
                for (int j = 0; j < 3; ++j) {
                    atomicAdd(crow + r0 * 4 + j, pc0[j]);
                    atomicAdd(crow + r1 * 4 + j, pc1[j]);
                }
            }
        }
    }
    __syncthreads();   // A writes visible to all warps
}

// ---------------- main kernel ----------------
__global__ void __launch_bounds__(NTHR, 2)
mesh_main(const int* __restrict__ verts, const float* __restrict__ barys,
          const float* __restrict__ views, const float* __restrict__ emb,
          float* __restrict__ out)
{
    extern __shared__ char sm[];
    uint32_t smb = smem_u32(sm);
    const int tid = threadIdx.x, lane = tid & 31, w = tid >> 5;
    const int base = blockIdx.x * MROWS;

    __half* AHI = (__half*)(sm + OFF_AHI);
    float* crow = (float*)(sm + OFF_CROW);

    // warp-private prefetch of layer-0 chunk 0 (overlaps gather)
    copy_w32(smb + OFF_WBUF + (uint32_t)w * 4096, g_wT[0][0], g_wT[0][1], 256, 0, lane, w * 16);

    if (tid < MROWS) {
        crow[tid * 4 + 0] = g_cbd[0]; crow[tid * 4 + 1] = g_cbd[1];
        crow[tid * 4 + 2] = g_cbd[2]; crow[tid * 4 + 3] = g_abd;
    }

    // ---- single-pass gather: blend (precomputed scales) -> fp16, color partials ----
    for (int r = w; r < MROWS; r += 16) {
        int grow = base + r;
        float v[8];
#pragma unroll
        for (int j = 0; j < 8; ++j) v[j] = 0.f;
#pragma unroll
        for (int vt = 0; vt < 3; ++vt) {
            int idx = verts[grow * 3 + vt] + 1;
            float s = barys[grow * 3 + vt] * __ldg(g_scale + (grow & 7) * NTAB + idx);
            const float* ep = emb + ((size_t)(grow & 7) * NTAB + (size_t)idx) * NC + lane * 8;
            float4 e0 = *(const float4*)ep, e1 = *(const float4*)(ep + 4);
            v[0] += s*e0.x; v[1] += s*e0.y; v[2] += s*e0.z; v[3] += s*e0.w;
            v[4] += s*e1.x; v[5] += s*e1.y; v[6] += s*e1.z; v[7] += s*e1.w;
        }
        int cbase = lane * 8;
#pragma unroll
        for (int p = 0; p < 4; ++p)
            *(uint32_t*)(AHI + r * ASTR + cbase + 2 * p) = pack_h2(v[2 * p], v[2 * p + 1]);
        float p0 = 0.f, p1 = 0.f, p2 = 0.f;
#pragma unroll
        for (int j = 0; j < 8; ++j) {
            const float* w3 = g_cWd + (size_t)(256 + cbase + j) * 3;
            p0 += v[j] * __ldg(w3); p1 += v[j] * __ldg(w3 + 1); p2 += v[j] * __ldg(w3 + 2);
        }
#pragma unroll
        for (int o = 16; o > 0; o >>= 1) {
            p0 += __shfl_xor_sync(~0u, p0, o);
            p1 += __shfl_xor_sync(~0u, p1, o);
            p2 += __shfl_xor_sync(~0u, p2, o);
        }
        if (lane == 0) {
            crow[r * 4 + 0] += p0; crow[r * 4 + 1] += p1; crow[r * 4 + 2] += p2;
        }
    }
    __syncthreads();

    // ---- vert branch ----
    do_layer<256, 0>(sm, smb, g_wT[0][0], g_wT[0][1], g_bias,       g_wT[1][0], g_wT[1][1], 256);
    do_layer<256, 2>(sm, smb, g_wT[1][0], g_wT[1][1], g_bias + 256, g_wP[0],    g_wP[1],    64);

    // ---- sincos -> A buf (K padded to 64) ----
    if (tid < MROWS) {
        int row = base + tid;
        float x0 = views[row * 3], x1 = views[row * 3 + 1], x2 = views[row * 3 + 2];
        float em[36];
#pragma unroll
        for (int l = 0; l < 6; ++l) {
            float f = (float)(1 << l);
            em[l * 6 + 0] = sinf(f * x0); em[l * 6 + 1] = sinf(f * x1); em[l * 6 + 2] = sinf(f * x2);
            em[l * 6 + 3] = cosf(f * x0); em[l * 6 + 4] = cosf(f * x1); em[l * 6 + 5] = cosf(f * x2);
        }
#pragma unroll
        for (int p = 0; p < 18; ++p)
            *(uint32_t*)(AHI + tid * ASTR + 2 * p) = pack_h2(em[2 * p], em[2 * p + 1]);
#pragma unroll
        for (int p = 18; p < 32; ++p)
            *(uint32_t*)(AHI + tid * ASTR + 2 * p) = 0u;
    }
    __syncthreads();

    // ---- view branch ----
    do_layer<64, 1>(sm, smb, g_wP[0], g_wP[1], g_bias + 512,          g_wT[2][0], g_wT[2][1], 256);
    do_layer<256, 0>(sm, smb, g_wT[2][0], g_wT[2][1], g_bias + 768,   g_wT[3][0], g_wT[3][1], 256);
    do_layer<256, 3>(sm, smb, g_wT[3][0], g_wT[3][1], g_bias + 1024,  (const __half*)0, (const __half*)0, 0);

    if (tid < MROWS) {
        float4 ov = make_float4(crow[tid * 4 + 0], crow[tid * 4 + 1],
                                crow[tid * 4 + 2], crow[tid * 4 + 3]);
        *(float4*)(out + (size_t)(base + tid) * 4) = ov;
    }
}

extern "C" void kernel_launch(void* const* d_in, const int* in_sizes, int n_in,
                              void* d_out, int out_size)
{
    const int*   verts  = (const int*)  d_in[0];
    const float* barys  = (const float*)d_in[1];
    const float* views  = (const float*)d_in[2];
    const float* emb    = (const float*)d_in[3];
    const float* w_proj = (const float*)d_in[4];
    const float* b_proj = (const float*)d_in[5];
    const float* view_W = (const float*)d_in[6];
    const float* view_b = (const float*)d_in[7];
    const float* vert_W = (const float*)d_in[8];
    const float* vert_b = (const float*)d_in[9];
    const float* aW1    = (const float*)d_in[10];
    const float* ab1    = (const float*)d_in[11];
    const float* aW2    = (const float*)d_in[12];
    const float* ab2    = (const float*)d_in[13];
    const float* cW1    = (const float*)d_in[14];
    const float* cb1    = (const float*)d_in[15];
    const float* cW2    = (const float*)d_in[16];
    const float* cb2    = (const float*)d_in[17];
    float* out = (float*)d_out;

    prep_norm<<<(8 * NTAB + 7) / 8, 256>>>(emb);
    prep_kernel<<<1100, 256>>>(w_proj, view_W, vert_W, aW1, ab1, aW2, ab2,
                               cW1, cb1, cW2, cb2, b_proj, view_b, vert_b);

    cudaFuncSetAttribute(mesh_main, cudaFuncAttributeMaxDynamicSharedMemorySize, SM_REQ);
    mesh_main<<<NROWS / MROWS, NTHR, SM_REQ>>>(verts, barys, views, emb, out);
}

// round 17
// speedup vs baseline: 1.2429x; 1.0256x over previous
#include <cuda_runtime.h>
#include <cuda_fp16.h>
#include <math.h>
#include <stdint.h>

#define NROWS 262144
#define NTAB  50001
#define NC    256
#define NTHR  512
#define MROWS 64

// SMEM byte offsets
#define OFF_AHI  0            // 64 x 264 fp16 = 33792
#define OFF_WBUF 33792        // 16 warps x 2 bufs x 2048B = 65536 -> 99328
#define OFF_CROW 99328        // 64 x 4 floats -> 100352
#define SM_REQ   100352
#define ASTR 264

__device__ __align__(16) __half g_wT[4][65536]; // [vert0,vert1,view0,view1][n*256+k], fp16
__device__ __align__(16) __half g_wP[16384];    // proj [n*64+k]
__device__ float g_cWd[1536], g_aWd[256], g_cbd[3], g_abd;
__device__ float g_bias[1280];   // vert_b(512) | b_proj(256) | view_b(512)
__device__ float g_scale[8 * NTAB];  // precomputed max_norm scales

// ---------------- low-level helpers ----------------
__device__ __forceinline__ uint32_t smem_u32(const void* p) {
    uint32_t a;
    asm("{ .reg .u64 t; cvta.to.shared.u64 t, %1; cvt.u32.u64 %0, t; }" : "=r"(a) : "l"(p));
    return a;
}
__device__ __forceinline__ void ldsm4(uint32_t r[4], uint32_t a) {
    asm volatile("ldmatrix.sync.aligned.m8n8.x4.shared.b16 {%0,%1,%2,%3}, [%4];"
        : "=r"(r[0]), "=r"(r[1]), "=r"(r[2]), "=r"(r[3]) : "r"(a));
}
__device__ __forceinline__ void mma16816(float c[4], const uint32_t a[4], uint32_t b0, uint32_t b1) {
    asm volatile("mma.sync.aligned.m16n8k16.row.col.f32.f16.f16.f32 "
        "{%0,%1,%2,%3},{%4,%5,%6,%7},{%8,%9},{%0,%1,%2,%3};"
        : "+f"(c[0]), "+f"(c[1]), "+f"(c[2]), "+f"(c[3])
        : "r"(a[0]), "r"(a[1]), "r"(a[2]), "r"(a[3]), "r"(b0), "r"(b1));
}
__device__ __forceinline__ void cp16(uint32_t d, const void* s) {
    asm volatile("cp.async.cg.shared.global [%0], [%1], 16;" :: "r"(d), "l"(s));
}
__device__ __forceinline__ uint32_t pack_h2(float f0, float f1) {
    __half2 h = __floats2half2_rn(f0, f1);
    return *(uint32_t*)&h;
}

// Warp-private copy: this warp's 16 N-rows x 64 K (fp16) -> given 2KB ring buffer.
// Row pitch 128B; 16B unit s of row r swizzled to ((s ^ (r & 7)) << 4).
__device__ __forceinline__ void copy_w64(uint32_t dst, const __half* src0,
        int kfull, int c, int lane, int nb0)
{
#pragma unroll
    for (int q = 0; q < 4; ++q) {
        int idx = q * 32 + lane;
        int r = idx >> 3, s = idx & 7;
        const __half* src = src0 + (size_t)(nb0 + r) * kfull + c * 64 + s * 8;
        uint32_t off = (uint32_t)(r * 128 + ((s ^ (r & 7)) << 4));
        cp16(dst + off, src);
    }
    asm volatile("cp.async.commit_group;");
}

// ---------------- prep kernels ----------------
__global__ void prep_norm(const float* __restrict__ emb) {
    int gid = blockIdx.x * 8 + (threadIdx.x >> 5);
    int lane = threadIdx.x & 31;
    if (gid >= 8 * NTAB) return;
    const float* ep = emb + (size_t)gid * NC + lane * 8;
    float4 e0 = *(const float4*)ep, e1 = *(const float4*)(ep + 4);
    float ss = e0.x*e0.x + e0.y*e0.y + e0.z*e0.z + e0.w*e0.w
             + e1.x*e1.x + e1.y*e1.y + e1.z*e1.z + e1.w*e1.w;
#pragma unroll
    for (int o = 16; o > 0; o >>= 1) ss += __shfl_xor_sync(~0u, ss, o);
    if (lane == 0) {
        float nrm = sqrtf(ss);
        g_scale[gid] = (nrm > 1.f) ? 1.f / fmaxf(nrm, 1e-7f) : 1.f;
    }
}

__global__ void prep_kernel(const float* __restrict__ w_proj, const float* __restrict__ view_W,
                            const float* __restrict__ vert_W,
                            const float* __restrict__ aW1, const float* __restrict__ ab1,
                            const float* __restrict__ aW2, const float* __restrict__ ab2,
                            const float* __restrict__ cW1, const float* __restrict__ cb1,
                            const float* __restrict__ cW2, const float* __restrict__ cb2,
                            const float* __restrict__ b_proj, const float* __restrict__ view_b,
                            const float* __restrict__ vert_b)
{
    int t = blockIdx.x * blockDim.x + threadIdx.x;
    if (t < 262144) {
        int layer = t >> 16, e = t & 65535, n = e >> 8, k = e & 255;
        const float* W = (layer < 2) ? (vert_W + layer * 65536) : (view_W + (layer - 2) * 65536);
        g_wT[layer][n * 256 + k] = __float2half_rn(W[k * 256 + n]);
    } else if (t < 262144 + 16384) {
        int e = t - 262144, n = e >> 6, k = e & 63;
        float w = (k < 36) ? w_proj[k * 256 + n] : 0.f;
        g_wP[n * 64 + k] = __float2half_rn(w);
    } else if (t < 262144 + 16384 + 1536) {
        int e = t - 262144 - 16384, kk = e / 3, j = e - kk * 3;
        float s = 0.f;
        for (int m = 0; m < 512; ++m) s += cW1[kk * 512 + m] * cW2[m * 3 + j];
        g_cWd[e] = s;
    } else if (t < 262144 + 16384 + 1536 + 3) {
        int j = t - 262144 - 16384 - 1536;
        float s = cb2[j];
        for (int m = 0; m < 512; ++m) s += cb1[m] * cW2[m * 3 + j];
        g_cbd[j] = s;
    } else if (t < 262144 + 16384 + 1536 + 3 + 256) {
        int kk = t - 262144 - 16384 - 1536 - 3;
        float s = 0.f;
        for (int m = 0; m < 256; ++m) s += aW1[kk * 256 + m] * aW2[m];
        g_aWd[kk] = s;
    } else if (t == 262144 + 16384 + 1536 + 3 + 256) {
        float s = ab2[0];
        for (int m = 0; m < 256; ++m) s += ab1[m] * aW2[m];
        g_abd = s;
    } else if (t >= 280064 && t < 280064 + 1280) {
        int i = t - 280064;
        float v;
        if (i < 512) v = vert_b[i];
        else if (i < 768) v = b_proj[i - 512];
        else v = view_b[i - 768];
        g_bias[i] = v;
    }
}

// ---------------- warp-autonomous fused layer (16 warps: each M64 x private N16) ----------------
// fp16 1-pass, 64-K chunks, 2-deep ring with explicit buffer phase pb.
// Precondition: this layer's chunk0 committed into buffer pb (1 group pending).
// Postcondition (if nx): next layer's chunk0 committed into buffer (nch+pb)&1.
// MODE 0: store relu; 1: store no-relu; 2: alpha head (relu); 3: color head (relu)
template<int KFULL, int MODE>
__device__ void do_layer(char* sm, uint32_t smb,
    const __half* __restrict__ Wg, const float* __restrict__ bias,
    const __half* nx, int nxK, int pb)
{
    const int tid = threadIdx.x, lane = tid & 31, w = tid >> 5;
    const int nb0 = w * 16;
    const int rowin = lane & 7, tsel = lane >> 3;

    float acc[4][2][4];
#pragma unroll
    for (int mt = 0; mt < 4; ++mt)
#pragma unroll
        for (int h = 0; h < 2; ++h)
#pragma unroll
            for (int j = 0; j < 4; ++j) acc[mt][h][j] = 0.f;

    const uint32_t aoffH = smb + OFF_AHI +
        (uint32_t)((rowin + (tsel & 1) * 8) * ASTR + (tsel >> 1) * 8) * 2;
    const int rowB = rowin + (tsel >> 1) * 8;
    const int sB   = tsel & 1;
    const uint32_t wreg = smb + OFF_WBUF + (uint32_t)w * 4096;

    const int nch = KFULL / 64;
    for (int c = 0; c < nch; ++c) {
        int f = c + 1;
        uint32_t nbuf = wreg + (uint32_t)((f + pb) & 1) * 2048;
        if (f < nch)      copy_w64(nbuf, Wg, KFULL, f, lane, nb0);
        else if (nx)      copy_w64(nbuf, nx, nxK, 0, lane, nb0);
        else              asm volatile("cp.async.commit_group;");
        asm volatile("cp.async.wait_group 1;" ::: "memory");
        __syncwarp();
        const uint32_t wb = wreg + (uint32_t)((c + pb) & 1) * 2048;
#pragma unroll
        for (int kk = 0; kk < 4; ++kk) {
            int su = 2 * kk + sB;
            uint32_t wo = (uint32_t)(rowB * 128 + ((su ^ (rowB & 7)) << 4));
            uint32_t wh[4];
            ldsm4(wh, wb + wo);
            const uint32_t kg2 = (uint32_t)(c * 128 + kk * 32);
#pragma unroll
            for (int mt = 0; mt < 4; ++mt) {
                uint32_t ah[4];
                ldsm4(ah, aoffH + kg2 + (uint32_t)mt * (16 * ASTR * 2));
                mma16816(acc[mt][0], ah, wh[0], wh[1]);
                mma16816(acc[mt][1], ah, wh[2], wh[3]);
            }
        }
    }

    // ---- epilogue (2 CTA barriers per layer) ----
    __syncthreads();   // all warps done reading A
    __half* AHI = (__half*)(sm + OFF_AHI);
    float* crow = (float*)(sm + OFF_CROW);

    float bb[2][2];
#pragma unroll
    for (int h = 0; h < 2; ++h) {
        int col = nb0 + h * 8 + (lane & 3) * 2;
        bb[h][0] = __ldg(bias + col);
        bb[h][1] = __ldg(bias + col + 1);
    }

#pragma unroll
    for (int mt = 0; mt < 4; ++mt) {
        int r0 = mt * 16 + (lane >> 2), r1 = r0 + 8;
        float pa0 = 0.f, pa1 = 0.f;
        float pc0[3] = {0.f, 0.f, 0.f}, pc1[3] = {0.f, 0.f, 0.f};
#pragma unroll
        for (int h = 0; h < 2; ++h) {
            int col = nb0 + h * 8 + (lane & 3) * 2;
            float* d = acc[mt][h];
            float f0 = d[0] + bb[h][0], f1 = d[1] + bb[h][1];
            float f2 = d[2] + bb[h][0], f3 = d[3] + bb[h][1];
            if (MODE != 1) {
                f0 = fmaxf(f0, 0.f); f1 = fmaxf(f1, 0.f);
                f2 = fmaxf(f2, 0.f); f3 = fmaxf(f3, 0.f);
            }
            if (MODE <= 1) {
                *(uint32_t*)(AHI + r0 * ASTR + col) = pack_h2(f0, f1);
                *(uint32_t*)(AHI + r1 * ASTR + col) = pack_h2(f2, f3);
            } else if (MODE == 2) {
                float w0 = __ldg(g_aWd + col), w1 = __ldg(g_aWd + col + 1);
                pa0 += f0 * w0 + f1 * w1;
                pa1 += f2 * w0 + f3 * w1;
            } else {
#pragma unroll
                for (int j = 0; j < 3; ++j) {
                    float w0 = __ldg(g_cWd + col * 3 + j), w1 = __ldg(g_cWd + (col + 1) * 3 + j);
                    pc0[j] += f0 * w0 + f1 * w1;
                    pc1[j] += f2 * w0 + f3 * w1;
                }
            }
        }
        if (MODE == 2) {
            pa0 += __shfl_xor_sync(~0u, pa0, 1); pa0 += __shfl_xor_sync(~0u, pa0, 2);
            pa1 += __shfl_xor_sync(~0u, pa1, 1); pa1 += __shfl_xor_sync(~0u, pa1, 2);
            if ((lane & 3) == 0) {
                atomicAdd(crow + r0 * 4 + 3, pa0);
                atomicAdd(crow + r1 * 4 + 3, pa1);
            }
        } else if (MODE == 3) {
#pragma unroll
            for (int j = 0; j < 3; ++j) {
                pc0[j] += __shfl_xor_sync(~0u, pc0[j], 1); pc0[j] += __shfl_xor_sync(~0u, pc0[j], 2);
                pc1[j] += __shfl_xor_sync(~0u, pc1[j], 1); pc1[j] += __shfl_xor_sync(~0u, pc1[j], 2);
            }
            if ((lane & 3) == 0) {
#pragma unroll
                for (int j = 0; j < 3; ++j) {
                    atomicAdd(crow + r0 * 4 + j, pc0[j]);
                    atomicAdd(crow + r1 * 4 + j, pc1[j]);
                }
            }
        }
    }
    __syncthreads();   // A writes visible to all warps
}

// ---------------- main kernel ----------------
__global__ void __launch_bounds__(NTHR, 2)
mesh_main(const int* __restrict__ verts, const float* __restrict__ barys,
          const float* __restrict__ views, const float* __restrict__ emb,
          float* __restrict__ out)
{
    extern __shared__ char sm[];
    uint32_t smb = smem_u32(sm);
    const int tid = threadIdx.x, lane = tid & 31, w = tid >> 5;
    const int base = blockIdx.x * MROWS;

    __half* AHI = (__half*)(sm + OFF_AHI);
    float* crow = (float*)(sm + OFF_CROW);

    // warp-private prefetch of layer-0 chunk 0 -> buffer 0 (pb=0)
    copy_w64(smb + OFF_WBUF + (uint32_t)w * 4096, g_wT[0], 256, 0, lane, w * 16);

    if (tid < MROWS) {
        crow[tid * 4 + 0] = g_cbd[0]; crow[tid * 4 + 1] = g_cbd[1];
        crow[tid * 4 + 2] = g_cbd[2]; crow[tid * 4 + 3] = g_abd;
    }

    // ---- single-pass gather: blend (precomputed scales) -> fp16, color partials ----
    for (int r = w; r < MROWS; r += 16) {
        int grow = base + r;
        float v[8];
#pragma unroll
        for (int j = 0; j < 8; ++j) v[j] = 0.f;
#pragma unroll
        for (int vt = 0; vt < 3; ++vt) {
            int idx = verts[grow * 3 + vt] + 1;
            float s = barys[grow * 3 + vt] * __ldg(g_scale + (grow & 7) * NTAB + idx);
            const float* ep = emb + ((size_t)(grow & 7) * NTAB + (size_t)idx) * NC + lane * 8;
            float4 e0 = *(const float4*)ep, e1 = *(const float4*)(ep + 4);
            v[0] += s*e0.x; v[1] += s*e0.y; v[2] += s*e0.z; v[3] += s*e0.w;
            v[4] += s*e1.x; v[5] += s*e1.y; v[6] += s*e1.z; v[7] += s*e1.w;
        }
        int cbase = lane * 8;
#pragma unroll
        for (int p = 0; p < 4; ++p)
            *(uint32_t*)(AHI + r * ASTR + cbase + 2 * p) = pack_h2(v[2 * p], v[2 * p + 1]);
        float p0 = 0.f, p1 = 0.f, p2 = 0.f;
#pragma unroll
        for (int j = 0; j < 8; ++j) {
            const float* w3 = g_cWd + (size_t)(256 + cbase + j) * 3;
            p0 += v[j] * __ldg(w3); p1 += v[j] * __ldg(w3 + 1); p2 += v[j] * __ldg(w3 + 2);
        }
#pragma unroll
        for (int o = 16; o > 0; o >>= 1) {
            p0 += __shfl_xor_sync(~0u, p0, o);
            p1 += __shfl_xor_sync(~0u, p1, o);
            p2 += __shfl_xor_sync(~0u, p2, o);
        }
        if (lane == 0) {
            crow[r * 4 + 0] += p0; crow[r * 4 + 1] += p1; crow[r * 4 + 2] += p2;
        }
    }
    __syncthreads();

    // ---- vert branch ----   (buffer phase: starts 0; nch=4 keeps parity, nch=1 flips)
    do_layer<256, 0>(sm, smb, g_wT[0], g_bias,       g_wT[1], 256, 0);
    do_layer<256, 2>(sm, smb, g_wT[1], g_bias + 256, g_wP,    64,  0);

    // ---- sincos -> A buf (K padded to 64) ----
    if (tid < MROWS) {
        int row = base + tid;
        float x0 = views[row * 3], x1 = views[row * 3 + 1], x2 = views[row * 3 + 2];
        float em[36];
#pragma unroll
        for (int l = 0; l < 6; ++l) {
            float f = (float)(1 << l);
            em[l * 6 + 0] = sinf(f * x0); em[l * 6 + 1] = sinf(f * x1); em[l * 6 + 2] = sinf(f * x2);
            em[l * 6 + 3] = cosf(f * x0); em[l * 6 + 4] = cosf(f * x1); em[l * 6 + 5] = cosf(f * x2);
        }
#pragma unroll
        for (int p = 0; p < 18; ++p)
            *(uint32_t*)(AHI + tid * ASTR + 2 * p) = pack_h2(em[2 * p], em[2 * p + 1]);
#pragma unroll
        for (int p = 18; p < 32; ++p)
            *(uint32_t*)(AHI + tid * ASTR + 2 * p) = 0u;
    }
    __syncthreads();

    // ---- view branch ----
    do_layer<64, 1>(sm, smb, g_wP, g_bias + 512,      g_wT[2], 256, 0);   // nch=1: flips parity
    do_layer<256, 0>(sm, smb, g_wT[2], g_bias + 768,  g_wT[3], 256, 1);
    do_layer<256, 3>(sm, smb, g_wT[3], g_bias + 1024, (const __half*)0, 0, 1);

    if (tid < MROWS) {
        float4 ov = make_float4(crow[tid * 4 + 0], crow[tid * 4 + 1],
                                crow[tid * 4 + 2], crow[tid * 4 + 3]);
        *(float4*)(out + (size_t)(base + tid) * 4) = ov;
    }
}

extern "C" void kernel_launch(void* const* d_in, const int* in_sizes, int n_in,
                              void* d_out, int out_size)
{
    const int*   verts  = (const int*)  d_in[0];
    const float* barys  = (const float*)d_in[1];
    const float* views  = (const float*)d_in[2];
    const float* emb    = (const float*)d_in[3];
    const float* w_proj = (const float*)d_in[4];
    const float* b_proj = (const float*)d_in[5];
    const float* view_W = (const float*)d_in[6];
    const float* view_b = (const float*)d_in[7];
    const float* vert_W = (const float*)d_in[8];
    const float* vert_b = (const float*)d_in[9];
    const float* aW1    = (const float*)d_in[10];
    const float* ab1    = (const float*)d_in[11];
    const float* aW2    = (const float*)d_in[12];
    const float* ab2    = (const float*)d_in[13];
    const float* cW1    = (const float*)d_in[14];
    const float* cb1    = (const float*)d_in[15];
    const float* cW2    = (const float*)d_in[16];
    const float* cb2    = (const float*)d_in[17];
    float* out = (float*)d_out;

    prep_norm<<<(8 * NTAB + 7) / 8, 256>>>(emb);
    prep_kernel<<<1100, 256>>>(w_proj, view_W, vert_W, aW1, ab1, aW2, ab2,
                               cW1, cb1, cW2, cb2, b_proj, view_b, vert_b);

    cudaFuncSetAttribute(mesh_main, cudaFuncAttributeMaxDynamicSharedMemorySize, SM_REQ);
    mesh_main<<<NROWS / MROWS, NTHR, SM_REQ>>>(verts, barys, views, emb, out);
}